// round 12
// baseline (speedup 1.0000x reference)
#include <cuda_runtime.h>
#include <cuda_fp16.h>
#include <cstdint>

#define N_TOKENS  131072
#define CODE_DIM  64
#define NUM_CODES 1024

// ---------------- device scratch (no allocations allowed) ----------------
__device__ float g_counts[NUM_CODES];
__device__ float g_dw[NUM_CODES * CODE_DIM];
__device__ float g_loss;
__device__ float g_ncs[NUM_CODES];
__device__ float g_n;
__device__ __align__(16) __half g_cb_h[NUM_CODES * CODE_DIM];
__device__ __align__(16) float g_cc[NUM_CODES];   // ||c||^2 + 256 (screen bias folded)

// ---------------- prep: zero scratch + fp16 codebook + cc ----------------
__global__ void vq_prep(const float* __restrict__ codebook) {
    int i = blockIdx.x * blockDim.x + threadIdx.x;   // 65536 threads
    g_dw[i] = 0.0f;
    if (i == 0) g_loss = 0.0f;
    if (i < NUM_CODES) {
        g_counts[i] = 0.0f;
        const float* c = codebook + (size_t)i * CODE_DIM;
        float s0 = 0.0f, s1 = 0.0f;
        #pragma unroll
        for (int k = 0; k < 32; k++) {
            float v = c[k];
            s0 += v * v;
            g_cb_h[i * CODE_DIM + k] = __float2half(v);
        }
        #pragma unroll
        for (int k = 32; k < 64; k++) {
            float v = c[k];
            s1 += v * v;
            g_cb_h[i * CODE_DIM + k] = __float2half(v);
        }
        g_cc[i] = (s0 + s1) + 256.0f;
    }
}

// ---------------- asm helpers ----------------
__device__ __forceinline__ void ldsm4(uint32_t (&r)[4], uint32_t addr) {
    asm volatile("ldmatrix.sync.aligned.m8n8.x4.shared.b16 {%0,%1,%2,%3}, [%4];"
                 : "=r"(r[0]), "=r"(r[1]), "=r"(r[2]), "=r"(r[3]) : "r"(addr));
}
__device__ __forceinline__ void mma16816(float (&d)[4], const uint32_t (&a)[4],
                                         const uint32_t* b) {
    asm volatile("mma.sync.aligned.m16n8k16.row.col.f32.f16.f16.f32 "
                 "{%0,%1,%2,%3}, {%4,%5,%6,%7}, {%8,%9}, {%0,%1,%2,%3};"
                 : "+f"(d[0]), "+f"(d[1]), "+f"(d[2]), "+f"(d[3])
                 : "r"(a[0]), "r"(a[1]), "r"(a[2]), "r"(a[3]),
                   "r"(b[0]), "r"(b[1]));
}
__device__ __forceinline__ void cp_async16(uint32_t dst, const void* src) {
    asm volatile("cp.async.cg.shared.global [%0], [%1], 16;" :: "r"(dst), "l"(src));
}
#define CP_COMMIT() asm volatile("cp.async.commit_group;")
#define CP_WAIT0()  asm volatile("cp.async.wait_group 0;" ::: "memory")

// exact round-2-style d2 (sequential-FMA dot, half-split sumsq, (zz-2a)+cc)
__device__ __forceinline__ float exact_d2_g(const float* __restrict__ zrow,
                                            const float* __restrict__ c, float zz) {
    float a = 0.0f;
    for (int k = 0; k < CODE_DIM; k++) a = fmaf(zrow[k], c[k], a);
    float c0 = 0.0f, c1 = 0.0f;
    for (int k = 0; k < 32; k++)  { float v = c[k]; c0 += v * v; }
    for (int k = 32; k < 64; k++) { float v = c[k]; c1 += v * v; }
    return (zz - 2.0f * a) + (c0 + c1);
}

// merge two sorted triples -> sorted top-3 of the six
__device__ __forceinline__ void merge3(unsigned long long& a1, unsigned long long& a2,
                                       unsigned long long& a3,
                                       unsigned long long b1, unsigned long long b2,
                                       unsigned long long b3) {
    unsigned long long lo1 = min(a1, b1), hi1 = max(a1, b1);
    unsigned long long lo2 = min(a2, b2), hi2 = max(a2, b2);
    a1 = lo1;
    unsigned long long t = min(hi1, lo2), u = max(hi1, lo2);
    a2 = t;
    a3 = min(u, min(hi2, min(a3, b3)));
}

// smem byte offsets (full fp16 codebook resident; no double buffering, no loop syncs)
#define OFF_ZH   0               // 128 x 72 fp16 = 18432
#define OFF_CH   18432           // 1024 x 72 fp16 (stride 144B, 128B data + 16B pad) = 147456
#define OFF_CC   165888          // 1024 floats = 4096
#define OFF_RED  169984          // 128 x 4 x 32B = 16384
#define OFF_LP   186368          // 32 floats
#define SMEM_TOTAL 186496

// ---------------- main: 1-pass fp16 mma screen + top-3 + exact rescore ----------------
// 256 threads, 8 warps as 2(M) x 4(N); block = 128 tokens x 1024 codes (8 tiles of 128).
// Entire codebook resident in smem -> main loop has ZERO barriers; warps drift so
// one warp's tensor-pipe mma overlaps the other's alu-pipe top-3 epilogue.
__global__ __launch_bounds__(256, 1)
void vq_main(const float* __restrict__ z, const float* __restrict__ codebook,
             float* __restrict__ out_q, float* __restrict__ out_idx)
{
    extern __shared__ char smem_raw[];
    char* sm = smem_raw;
    const uint32_t sbase = (uint32_t)__cvta_generic_to_shared(sm);

    const int tid = threadIdx.x;
    const int token0 = blockIdx.x * 128;
    const int lane = tid & 31, wid = tid >> 5;
    const int wm = wid >> 2, wn = wid & 3;
    const int lrow = lane & 7, lmat = lane >> 3;
    const int g = lane >> 2, q4 = lane & 3;

    // ---- stage ENTIRE fp16 codebook (128 KB) + cc via cp.async ----
    #pragma unroll
    for (int j = 0; j < 32; j++) {
        int c = tid + j * 256;                 // 0..8191 16B chunks (8 per row of 1024)
        int r = c >> 3, k16 = c & 7;
        const __half* src = g_cb_h + (size_t)r * 64 + k16 * 8;
        cp_async16(sbase + OFF_CH + r * 144 + k16 * 16, src);
    }
    cp_async16(sbase + OFF_CC + tid * 16, g_cc + tid * 4);
    CP_COMMIT();

    // ---- z tile: fp16 into smem (stride 72 halves) ----
    {
        int r = tid >> 1, h = tid & 1;
        const float4* zp = (const float4*)(z + (size_t)(token0 + r) * CODE_DIM) + h * 8;
        __half* zh = (__half*)(sm + OFF_ZH) + r * 72 + h * 32;
        #pragma unroll
        for (int v = 0; v < 8; v++) {
            float4 t4 = zp[v];
            zh[v * 4 + 0] = __float2half(t4.x);
            zh[v * 4 + 1] = __float2half(t4.y);
            zh[v * 4 + 2] = __float2half(t4.z);
            zh[v * 4 + 3] = __float2half(t4.w);
        }
    }

    CP_WAIT0();
    __syncthreads();   // z + codebook + cc all resident; no more barriers until reduction

    // ldmatrix addressing (proven R5/R9 mapping)
    const int a_row = wm * 64 + (lmat & 1) * 8 + lrow;
    const int a_kof = (lmat >> 1) * 8;
    const int b_row = wn * 32 + (lmat >> 1) * 8 + lrow;
    const int b_kof = (lmat & 1) * 8;

    // preload A fragments once (z reused across all 8 tiles)
    uint32_t ah[4][4][4];   // [kc][mf][frag]
    #pragma unroll
    for (int kc = 0; kc < 4; kc++)
        #pragma unroll
        for (int mf = 0; mf < 4; mf++) {
            uint32_t off = (uint32_t)(((a_row + mf * 16) * 72 + kc * 16 + a_kof) * 2);
            ldsm4(ah[kc][mf], sbase + OFF_ZH + off);
        }

    // sorted top-3 trackers per (row, c): keys = (bits(s)&~31) | (ct*4+nf)
    int k3[8][2][3];
    #pragma unroll
    for (int r = 0; r < 8; r++)
        #pragma unroll
        for (int c = 0; c < 2; c++) {
            k3[r][c][0] = 0x7FFFFFFF; k3[r][c][1] = 0x7FFFFFFF; k3[r][c][2] = 0x7FFFFFFF;
        }

    const float* ccs_all = (const float*)(sm + OFF_CC);

    for (int ct = 0; ct < 8; ct++) {
        float ccr[8];
        #pragma unroll
        for (int nf = 0; nf < 4; nf++)
            #pragma unroll
            for (int c = 0; c < 2; c++)
                ccr[nf * 2 + c] = ccs_all[ct * 128 + wn * 32 + nf * 8 + q4 * 2 + c];

        float acc[4][4][4];
        #pragma unroll
        for (int mf = 0; mf < 4; mf++)
            #pragma unroll
            for (int nf = 0; nf < 4; nf++)
                #pragma unroll
                for (int e = 0; e < 4; e++) acc[mf][nf][e] = 0.0f;

        #pragma unroll
        for (int kc = 0; kc < 4; kc++) {
            uint32_t bh[2][4];
            #pragma unroll
            for (int np = 0; np < 2; np++) {
                uint32_t off = (uint32_t)(((ct * 128 + b_row + np * 16) * 72
                                           + kc * 16 + b_kof) * 2);
                ldsm4(bh[np], sbase + OFF_CH + off);
            }
            #pragma unroll
            for (int mf = 0; mf < 4; mf++)
                #pragma unroll
                for (int nf = 0; nf < 4; nf++)
                    mma16816(acc[mf][nf], ah[kc][mf], &bh[nf >> 1][(nf & 1) * 2]);
        }

        // ---- epilogue: s = (cc+256) - 2*dot, sorted top-3 insert (branch-free) ----
        const int idb = ct * 4;
        #pragma unroll
        for (int mf = 0; mf < 4; mf++)
            #pragma unroll
            for (int rr = 0; rr < 2; rr++) {
                const int row = mf * 2 + rr;
                #pragma unroll
                for (int nf = 0; nf < 4; nf++)
                    #pragma unroll
                    for (int c = 0; c < 2; c++) {
                        float s = fmaf(acc[mf][nf][rr * 2 + c], -2.0f, ccr[nf * 2 + c]);
                        int key = (__float_as_int(s) & 0xFFFFFFE0) | (idb + nf);
                        int t1 = max(k3[row][c][0], key);
                        k3[row][c][0] = min(k3[row][c][0], key);
                        int t2 = max(k3[row][c][1], t1);
                        k3[row][c][1] = min(k3[row][c][1], t1);
                        k3[row][c][2] = min(k3[row][c][2], t2);
                    }
            }
    }

    // ---- per-row: 64-bit keys, merge trackers + quad shfl, stash per (token, wn) ----
    ulonglong4* red = (ulonglong4*)(sm + OFF_RED);
    const int base_nc = wn * 32 + q4 * 2;
    #pragma unroll
    for (int row = 0; row < 8; row++) {
        unsigned long long m1, m2, m3;
        {
            unsigned long long kk[2][3];
            #pragma unroll
            for (int c = 0; c < 2; c++)
                #pragma unroll
                for (int j = 0; j < 3; j++) {
                    int k = k3[row][c][j];
                    int id = k & 31;
                    unsigned long long code =
                        (unsigned)((id >> 2) * 128 + (id & 3) * 8 + base_nc + c);
                    kk[c][j] = ((unsigned long long)(unsigned)(k & 0xFFFFFFE0) << 10) | code;
                }
            m1 = kk[0][0]; m2 = kk[0][1]; m3 = kk[0][2];
            merge3(m1, m2, m3, kk[1][0], kk[1][1], kk[1][2]);
        }
        #pragma unroll
        for (int m = 1; m <= 2; m <<= 1) {
            unsigned long long M1 = __shfl_xor_sync(0xffffffffu, m1, m);
            unsigned long long M2 = __shfl_xor_sync(0xffffffffu, m2, m);
            unsigned long long M3 = __shfl_xor_sync(0xffffffffu, m3, m);
            merge3(m1, m2, m3, M1, M2, M3);
        }
        if (q4 == 0) {
            int tok = wm * 64 + (row >> 1) * 16 + (row & 1) * 8 + g;
            red[tok * 4 + wn] = make_ulonglong4(m1, m2, m3, 0ull);
        }
    }
    __syncthreads();

    // ---- writer: final merge, rescore near-ties, outputs + scatter stats ----
    float lsum = 0.0f;
    if (tid < 128) {
        const int t = tid;
        ulonglong4 p = red[t * 4];
        unsigned long long f1 = p.x, f2 = p.y, f3 = p.z;
        #pragma unroll
        for (int w = 1; w < 4; w++) {
            ulonglong4 q = red[t * 4 + w];
            merge3(f1, f2, f3, q.x, q.y, q.z);
        }
        int bi = (int)(f1 & 1023);
        const int token = token0 + t;
        const float* zrow = z + (size_t)token * CODE_DIM;

        float s1 = __int_as_float((int)(f1 >> 10));
        float s2 = __int_as_float((int)(f2 >> 10));
        if (s2 - s1 < 0.1f) {
            // near-tie: exact rescore of the screened top-3 (verified arithmetic)
            int c2 = (int)(f2 & 1023), c3 = (int)(f3 & 1023);
            float a0 = 0.0f, a1 = 0.0f;
            for (int k = 0; k < 32; k++)  { float v = zrow[k]; a0 += v * v; }
            for (int k = 32; k < 64; k++) { float v = zrow[k]; a1 += v * v; }
            float zz = a0 + a1;
            float d1 = exact_d2_g(zrow, codebook + (size_t)bi * CODE_DIM, zz);
            float d2 = exact_d2_g(zrow, codebook + (size_t)c2 * CODE_DIM, zz);
            float d3 = exact_d2_g(zrow, codebook + (size_t)c3 * CODE_DIM, zz);
            float bd = d1;
            if (d2 < bd || (d2 == bd && c2 < bi)) { bd = d2; bi = c2; }
            if (d3 < bd || (d3 == bd && c3 < bi)) { bd = d3; bi = c3; }
        }

        out_idx[token] = (float)bi;
        atomicAdd(&g_counts[bi], 1.0f);

        const float4* cb = (const float4*)(codebook + (size_t)bi * CODE_DIM);
        const float4* zp = (const float4*)zrow;
        float4* qo = (float4*)(out_q + (size_t)token * CODE_DIM);
        #pragma unroll
        for (int v = 0; v < 16; v++) {
            float4 q = cb[v];
            float4 zv = zp[v];
            int k = v * 4;
            float d0 = zv.x - q.x, d1 = zv.y - q.y, d2 = zv.z - q.z, d3 = zv.w - q.w;
            lsum += d0 * d0; lsum += d1 * d1; lsum += d2 * d2; lsum += d3 * d3;
            qo[v] = q;
            atomicAdd(&g_dw[bi * CODE_DIM + k + 0], zv.x);
            atomicAdd(&g_dw[bi * CODE_DIM + k + 1], zv.y);
            atomicAdd(&g_dw[bi * CODE_DIM + k + 2], zv.z);
            atomicAdd(&g_dw[bi * CODE_DIM + k + 3], zv.w);
        }
    }

    // ---- block reduction of commitment-loss partial ----
    #pragma unroll
    for (int o = 16; o > 0; o >>= 1) lsum += __shfl_down_sync(0xffffffffu, lsum, o);
    float* lpart = (float*)(sm + OFF_LP);
    if ((tid & 31) == 0) lpart[tid >> 5] = lsum;
    __syncthreads();
    if (tid == 0) {
        float s = 0.0f;
        #pragma unroll
        for (int w = 0; w < 8; w++) s += lpart[w];
        atomicAdd(&g_loss, s);
    }
}

// ---------------- finalize 1: new_cluster_size + its sum ----------------
__global__ void vq_final_cs(const float* __restrict__ cluster_size,
                            float* __restrict__ out_cs)
{
    int t = threadIdx.x;  // 1024 threads, 1 block
    float ncs = 0.99f * cluster_size[t] + 0.01f * g_counts[t];
    out_cs[t] = ncs;
    g_ncs[t] = ncs;

    float s = ncs;
    #pragma unroll
    for (int o = 16; o > 0; o >>= 1) s += __shfl_down_sync(0xffffffffu, s, o);
    __shared__ float p[32];
    if ((t & 31) == 0) p[t >> 5] = s;
    __syncthreads();
    if (t < 32) {
        float v = p[t];
        #pragma unroll
        for (int o = 16; o > 0; o >>= 1) v += __shfl_down_sync(0xffffffffu, v, o);
        if (t == 0) g_n = v;
    }
}

// ---------------- finalize 2: new_ema_w, new_codebook, loss ----------------
__global__ void vq_final_cb(const float* __restrict__ ema_w,
                            float* __restrict__ out_ew,
                            float* __restrict__ out_cb,
                            float* __restrict__ out_loss)
{
    int i = blockIdx.x * blockDim.x + threadIdx.x;  // 65536
    float e = 0.99f * ema_w[i] + 0.01f * g_dw[i];
    out_ew[i] = e;
    int k = i >> 6;
    float n = g_n;
    float cs = (g_ncs[k] + 1e-5f) / (n + 1024.0f * 1e-5f) * n;
    out_cb[i] = e / cs;
    if (i == 0) out_loss[0] = g_loss * (1.0f / 8388608.0f);  // 2^-23 == 1/(N*D)
}

// ---------------- launch ----------------
extern "C" void kernel_launch(void* const* d_in, const int* in_sizes, int n_in,
                              void* d_out, int out_size)
{
    const float* z            = (const float*)d_in[0];
    const float* codebook     = (const float*)d_in[1];
    const float* cluster_size = (const float*)d_in[2];
    const float* ema_w        = (const float*)d_in[3];
    float* out = (float*)d_out;

    // output packing: quantized_st | indices | loss | new_codebook | new_cluster_size | new_ema_w
    const size_t OFF_Q    = 0;
    const size_t OFF_IDX  = (size_t)N_TOKENS * CODE_DIM;          // 8388608
    const size_t OFF_LOSS = OFF_IDX + N_TOKENS;                   // 8519680
    const size_t OFF_CB   = OFF_LOSS + 1;                         // 8519681
    const size_t OFF_CS   = OFF_CB + NUM_CODES * CODE_DIM;        // 8585217
    const size_t OFF_EW   = OFF_CS + NUM_CODES;                   // 8586241

    cudaFuncSetAttribute(vq_main, cudaFuncAttributeMaxDynamicSharedMemorySize, SMEM_TOTAL);

    vq_prep<<<256, 256>>>(codebook);
    vq_main<<<N_TOKENS / 128, 256, SMEM_TOTAL>>>(z, codebook, out + OFF_Q, out + OFF_IDX);
    vq_final_cs<<<1, NUM_CODES>>>(cluster_size, out + OFF_CS);
    vq_final_cb<<<(NUM_CODES * CODE_DIM) / 256, 256>>>(ema_w, out + OFF_EW,
                                                       out + OFF_CB, out + OFF_LOSS);
}

// round 14
// speedup vs baseline: 1.0524x; 1.0524x over previous
#include <cuda_runtime.h>
#include <cuda_fp16.h>
#include <cstdint>

#define N_TOKENS  131072
#define CODE_DIM  64
#define NUM_CODES 1024

// ---------------- device scratch (no allocations allowed) ----------------
__device__ float g_counts[NUM_CODES];
__device__ float g_dw[NUM_CODES * CODE_DIM];
__device__ float g_loss;
__device__ float g_ncs[NUM_CODES];
__device__ float g_n;
__device__ __align__(16) __half g_cb_h[NUM_CODES * CODE_DIM];
__device__ __align__(16) float g_cc[NUM_CODES];   // ||c||^2 + 256 (screen bias folded)

// ---------------- prep: zero scratch + fp16 codebook + cc ----------------
__global__ void vq_prep(const float* __restrict__ codebook) {
    int i = blockIdx.x * blockDim.x + threadIdx.x;   // 65536 threads
    g_dw[i] = 0.0f;
    if (i == 0) g_loss = 0.0f;
    if (i < NUM_CODES) {
        g_counts[i] = 0.0f;
        const float* c = codebook + (size_t)i * CODE_DIM;
        float s0 = 0.0f, s1 = 0.0f;
        #pragma unroll
        for (int k = 0; k < 32; k++) {
            float v = c[k];
            s0 += v * v;
            g_cb_h[i * CODE_DIM + k] = __float2half(v);
        }
        #pragma unroll
        for (int k = 32; k < 64; k++) {
            float v = c[k];
            s1 += v * v;
            g_cb_h[i * CODE_DIM + k] = __float2half(v);
        }
        g_cc[i] = (s0 + s1) + 256.0f;
    }
}

// ---------------- asm helpers ----------------
__device__ __forceinline__ void ldsm4(uint32_t (&r)[4], uint32_t addr) {
    asm volatile("ldmatrix.sync.aligned.m8n8.x4.shared.b16 {%0,%1,%2,%3}, [%4];"
                 : "=r"(r[0]), "=r"(r[1]), "=r"(r[2]), "=r"(r[3]) : "r"(addr));
}
__device__ __forceinline__ void mma16816(float (&d)[4], const uint32_t (&a)[4],
                                         const uint32_t* b) {
    asm volatile("mma.sync.aligned.m16n8k16.row.col.f32.f16.f16.f32 "
                 "{%0,%1,%2,%3}, {%4,%5,%6,%7}, {%8,%9}, {%0,%1,%2,%3};"
                 : "+f"(d[0]), "+f"(d[1]), "+f"(d[2]), "+f"(d[3])
                 : "r"(a[0]), "r"(a[1]), "r"(a[2]), "r"(a[3]),
                   "r"(b[0]), "r"(b[1]));
}
__device__ __forceinline__ void cp_async16(uint32_t dst, const void* src) {
    asm volatile("cp.async.cg.shared.global [%0], [%1], 16;" :: "r"(dst), "l"(src));
}
#define CP_COMMIT() asm volatile("cp.async.commit_group;")
#define CP_WAIT1()  asm volatile("cp.async.wait_group 1;" ::: "memory")
#define CP_WAIT0()  asm volatile("cp.async.wait_group 0;" ::: "memory")

// exact round-2-style d2 (sequential-FMA dot, half-split sumsq, (zz-2a)+cc)
__device__ __forceinline__ float exact_d2_g(const float* __restrict__ zrow,
                                            const float* __restrict__ c, float zz) {
    float a = 0.0f;
    for (int k = 0; k < CODE_DIM; k++) a = fmaf(zrow[k], c[k], a);
    float c0 = 0.0f, c1 = 0.0f;
    for (int k = 0; k < 32; k++)  { float v = c[k]; c0 += v * v; }
    for (int k = 32; k < 64; k++) { float v = c[k]; c1 += v * v; }
    return (zz - 2.0f * a) + (c0 + c1);
}

// merge two sorted triples -> sorted top-3 of the six
__device__ __forceinline__ void merge3(unsigned long long& a1, unsigned long long& a2,
                                       unsigned long long& a3,
                                       unsigned long long b1, unsigned long long b2,
                                       unsigned long long b3) {
    unsigned long long lo1 = min(a1, b1), hi1 = max(a1, b1);
    unsigned long long lo2 = min(a2, b2), hi2 = max(a2, b2);
    a1 = lo1;
    unsigned long long t = min(hi1, lo2), u = max(hi1, lo2);
    a2 = t;
    a3 = min(u, min(hi2, min(a3, b3)));
}

// smem byte offsets (R9 layout)
#define OFF_ZH   0               // 128 x 72 fp16 = 18432
#define OFF_CH   18432           // 2 bufs x 18432
#define OFF_CC   55296           // 2 bufs x 512
#define OFF_RED  56320           // 128 x 4 x 32B = 16384
#define OFF_LP   72704           // 32 floats
#define SMEM_TOTAL 72832

// deferred epilogue: s = (cc+256) - 2*dot over one acc set; 6-bit id keys, sorted top-3
__device__ __forceinline__ void epi_step(const float (&acc)[4][4][4], const float (&ccr)[8],
                                         int idb6, int (&k3)[8][3]) {
    #pragma unroll
    for (int mf = 0; mf < 4; mf++)
        #pragma unroll
        for (int rr = 0; rr < 2; rr++) {
            const int row = mf * 2 + rr;
            #pragma unroll
            for (int nf = 0; nf < 4; nf++)
                #pragma unroll
                for (int c = 0; c < 2; c++) {
                    float s = fmaf(acc[mf][nf][rr * 2 + c], -2.0f, ccr[nf * 2 + c]);
                    int key = (__float_as_int(s) & 0xFFFFFFC0) | (idb6 + nf * 2 + c);
                    int t1 = max(k3[row][0], key);
                    k3[row][0] = min(k3[row][0], key);
                    int t2 = max(k3[row][1], t1);
                    k3[row][1] = min(k3[row][1], t1);
                    k3[row][2] = min(k3[row][2], t2);
                }
        }
}

// ---------------- main: 1-pass fp16 mma screen + deferred epilogue + exact rescore --------
// 256 threads, 8 warps as 2(M) x 4(N); block = 128 tokens x 1024 codes (8 tiles of 128).
// Double accumulator sets: tile ct's HMMAs are in flight while tile ct-1's top-3
// epilogue runs (no register dependence) -> epilogue ALU hides under tensor pipe.
__global__ __launch_bounds__(256, 1)
void vq_main(const float* __restrict__ z, const float* __restrict__ codebook,
             float* __restrict__ out_q, float* __restrict__ out_idx)
{
    extern __shared__ char smem_raw[];
    char* sm = smem_raw;
    const uint32_t sbase = (uint32_t)__cvta_generic_to_shared(sm);

    const int tid = threadIdx.x;
    const int token0 = blockIdx.x * 128;
    const int lane = tid & 31, wid = tid >> 5;
    const int wm = wid >> 2, wn = wid & 3;
    const int lrow = lane & 7, lmat = lane >> 3;
    const int g = lane >> 2, q4 = lane & 3;

    // ---- prefetch codebook tile 0 (buf 0) + cc via cp.async ----
    #pragma unroll
    for (int j = 0; j < 4; j++) {
        int c = tid + j * 256;                 // 0..1023 16B chunks
        int r = c >> 3, k16 = c & 7;
        const __half* src = g_cb_h + (size_t)r * 64 + k16 * 8;
        cp_async16(sbase + OFF_CH + r * 144 + k16 * 16, src);
    }
    if (tid < 32) cp_async16(sbase + OFF_CC + tid * 16, g_cc + tid * 4);
    CP_COMMIT();

    // ---- z tile: fp16 into smem (stride 72 halves) ----
    {
        int r = tid >> 1, h = tid & 1;
        const float4* zp = (const float4*)(z + (size_t)(token0 + r) * CODE_DIM) + h * 8;
        __half* zh = (__half*)(sm + OFF_ZH) + r * 72 + h * 32;
        #pragma unroll
        for (int v = 0; v < 8; v++) {
            float4 t4 = zp[v];
            zh[v * 4 + 0] = __float2half(t4.x);
            zh[v * 4 + 1] = __float2half(t4.y);
            zh[v * 4 + 2] = __float2half(t4.z);
            zh[v * 4 + 3] = __float2half(t4.w);
        }
    }

    // ldmatrix addressing (proven R5/R9 mapping)
    const int a_row = wm * 64 + (lmat & 1) * 8 + lrow;
    const int a_kof = (lmat >> 1) * 8;
    const int b_row = wn * 32 + (lmat >> 1) * 8 + lrow;
    const int b_kof = (lmat & 1) * 8;

    // sorted top-3 trackers per row (joint over c): keys = (bits(s)&~63) | (ct*8+nf*2+c)
    int k3[8][3];
    #pragma unroll
    for (int r = 0; r < 8; r++) {
        k3[r][0] = 0x7FFFFFFF; k3[r][1] = 0x7FFFFFFF; k3[r][2] = 0x7FFFFFFF;
    }

    float acc[2][4][4][4];     // double accumulator sets (pipeline)
    float ccr[2][8];           // cc values for each in-flight tile

    for (int ct = 0; ct < 8; ct++) {
        const int b = ct & 1;
        if (ct < 7) {        // prefetch tile ct+1 into buf b^1
            const int nb = b ^ 1;
            #pragma unroll
            for (int j = 0; j < 4; j++) {
                int c = tid + j * 256;
                int r = c >> 3, k16 = c & 7;
                const __half* src = g_cb_h + (size_t)((ct + 1) * 128 + r) * 64 + k16 * 8;
                cp_async16(sbase + OFF_CH + nb * 18432 + r * 144 + k16 * 16, src);
            }
            if (tid < 32) cp_async16(sbase + OFF_CC + nb * 512 + tid * 16,
                                     g_cc + (ct + 1) * 128 + tid * 4);
            CP_COMMIT();
            CP_WAIT1();
        } else {
            CP_WAIT0();
        }
        __syncthreads();     // tile ct staged & visible to all warps

        // cc for tile ct -> regs (consumed by deferred epilogue next iteration)
        const float* ccs = (const float*)(sm + OFF_CC + b * 512);
        #pragma unroll
        for (int nf = 0; nf < 4; nf++)
            #pragma unroll
            for (int c = 0; c < 2; c++)
                ccr[b][nf * 2 + c] = ccs[wn * 32 + nf * 8 + q4 * 2 + c];

        // ldsm B + issue HMMAs into acc[b]
        #pragma unroll
        for (int mf = 0; mf < 4; mf++)
            #pragma unroll
            for (int nf = 0; nf < 4; nf++)
                #pragma unroll
                for (int e = 0; e < 4; e++) acc[b][mf][nf][e] = 0.0f;

        const uint32_t s_ch = sbase + OFF_CH + b * 18432;
        #pragma unroll
        for (int kc = 0; kc < 4; kc++) {
            uint32_t ah[4][4], bh[2][4];
            #pragma unroll
            for (int mf = 0; mf < 4; mf++) {
                uint32_t off = (uint32_t)(((a_row + mf * 16) * 72 + kc * 16 + a_kof) * 2);
                ldsm4(ah[mf], sbase + OFF_ZH + off);
            }
            #pragma unroll
            for (int np = 0; np < 2; np++) {
                uint32_t off = (uint32_t)(((b_row + np * 16) * 72 + kc * 16 + b_kof) * 2);
                ldsm4(bh[np], s_ch + off);
            }
            #pragma unroll
            for (int mf = 0; mf < 4; mf++)
                #pragma unroll
                for (int nf = 0; nf < 4; nf++)
                    mma16816(acc[b][mf][nf], ah[mf], &bh[nf >> 1][(nf & 1) * 2]);
        }

        // deferred epilogue of tile ct-1 (independent regs -> overlaps in-flight HMMAs)
        if (ct > 0) epi_step(acc[b ^ 1], ccr[b ^ 1], (ct - 1) * 8, k3);

        __syncthreads();     // all ldsm reads of buf b done before it is restaged
    }
    // tail epilogue: tile 7 (acc set 1)
    epi_step(acc[1], ccr[1], 56, k3);

    // ---- per-row: 64-bit keys (sorted already), quad shfl merge, stash per (token, wn) ----
    ulonglong4* red = (ulonglong4*)(sm + OFF_RED);
    const int base_nc = wn * 32 + q4 * 2;
    #pragma unroll
    for (int row = 0; row < 8; row++) {
        unsigned long long m1, m2, m3;
        {
            unsigned long long kk[3];
            #pragma unroll
            for (int j = 0; j < 3; j++) {
                int k = k3[row][j];
                int id6 = k & 63;
                unsigned long long code =
                    (unsigned)((id6 >> 3) * 128 + ((id6 >> 1) & 3) * 8 + base_nc + (id6 & 1));
                kk[j] = ((unsigned long long)(unsigned)(k & 0xFFFFFFC0) << 10) | code;
            }
            m1 = kk[0]; m2 = kk[1]; m3 = kk[2];
        }
        #pragma unroll
        for (int m = 1; m <= 2; m <<= 1) {
            unsigned long long M1 = __shfl_xor_sync(0xffffffffu, m1, m);
            unsigned long long M2 = __shfl_xor_sync(0xffffffffu, m2, m);
            unsigned long long M3 = __shfl_xor_sync(0xffffffffu, m3, m);
            merge3(m1, m2, m3, M1, M2, M3);
        }
        if (q4 == 0) {
            int tok = wm * 64 + (row >> 1) * 16 + (row & 1) * 8 + g;
            red[tok * 4 + wn] = make_ulonglong4(m1, m2, m3, 0ull);
        }
    }
    __syncthreads();

    // ---- writer: final merge, rescore near-ties, outputs + scatter stats ----
    float lsum = 0.0f;
    if (tid < 128) {
        const int t = tid;
        ulonglong4 p = red[t * 4];
        unsigned long long f1 = p.x, f2 = p.y, f3 = p.z;
        #pragma unroll
        for (int w = 1; w < 4; w++) {
            ulonglong4 q = red[t * 4 + w];
            merge3(f1, f2, f3, q.x, q.y, q.z);
        }
        int bi = (int)(f1 & 1023);
        const int token = token0 + t;
        const float* zrow = z + (size_t)token * CODE_DIM;

        float s1 = __int_as_float((int)(f1 >> 10));
        float s2 = __int_as_float((int)(f2 >> 10));
        if (s2 - s1 < 0.1f) {
            // near-tie: exact rescore of the screened top-3 (verified arithmetic)
            int c2 = (int)(f2 & 1023), c3 = (int)(f3 & 1023);
            float a0 = 0.0f, a1 = 0.0f;
            for (int k = 0; k < 32; k++)  { float v = zrow[k]; a0 += v * v; }
            for (int k = 32; k < 64; k++) { float v = zrow[k]; a1 += v * v; }
            float zz = a0 + a1;
            float d1 = exact_d2_g(zrow, codebook + (size_t)bi * CODE_DIM, zz);
            float d2 = exact_d2_g(zrow, codebook + (size_t)c2 * CODE_DIM, zz);
            float d3 = exact_d2_g(zrow, codebook + (size_t)c3 * CODE_DIM, zz);
            float bd = d1;
            if (d2 < bd || (d2 == bd && c2 < bi)) { bd = d2; bi = c2; }
            if (d3 < bd || (d3 == bd && c3 < bi)) { bd = d3; bi = c3; }
        }

        out_idx[token] = (float)bi;
        atomicAdd(&g_counts[bi], 1.0f);

        const float4* cb = (const float4*)(codebook + (size_t)bi * CODE_DIM);
        const float4* zp = (const float4*)zrow;
        float4* qo = (float4*)(out_q + (size_t)token * CODE_DIM);
        #pragma unroll
        for (int v = 0; v < 16; v++) {
            float4 q = cb[v];
            float4 zv = zp[v];
            int k = v * 4;
            float d0 = zv.x - q.x, d1 = zv.y - q.y, d2 = zv.z - q.z, d3 = zv.w - q.w;
            lsum += d0 * d0; lsum += d1 * d1; lsum += d2 * d2; lsum += d3 * d3;
            qo[v] = q;
            atomicAdd(&g_dw[bi * CODE_DIM + k + 0], zv.x);
            atomicAdd(&g_dw[bi * CODE_DIM + k + 1], zv.y);
            atomicAdd(&g_dw[bi * CODE_DIM + k + 2], zv.z);
            atomicAdd(&g_dw[bi * CODE_DIM + k + 3], zv.w);
        }
    }

    // ---- block reduction of commitment-loss partial ----
    #pragma unroll
    for (int o = 16; o > 0; o >>= 1) lsum += __shfl_down_sync(0xffffffffu, lsum, o);
    float* lpart = (float*)(sm + OFF_LP);
    if ((tid & 31) == 0) lpart[tid >> 5] = lsum;
    __syncthreads();
    if (tid == 0) {
        float s = 0.0f;
        #pragma unroll
        for (int w = 0; w < 8; w++) s += lpart[w];
        atomicAdd(&g_loss, s);
    }
}

// ---------------- finalize 1: new_cluster_size + its sum ----------------
__global__ void vq_final_cs(const float* __restrict__ cluster_size,
                            float* __restrict__ out_cs)
{
    int t = threadIdx.x;  // 1024 threads, 1 block
    float ncs = 0.99f * cluster_size[t] + 0.01f * g_counts[t];
    out_cs[t] = ncs;
    g_ncs[t] = ncs;

    float s = ncs;
    #pragma unroll
    for (int o = 16; o > 0; o >>= 1) s += __shfl_down_sync(0xffffffffu, s, o);
    __shared__ float p[32];
    if ((t & 31) == 0) p[t >> 5] = s;
    __syncthreads();
    if (t < 32) {
        float v = p[t];
        #pragma unroll
        for (int o = 16; o > 0; o >>= 1) v += __shfl_down_sync(0xffffffffu, v, o);
        if (t == 0) g_n = v;
    }
}

// ---------------- finalize 2: new_ema_w, new_codebook, loss ----------------
__global__ void vq_final_cb(const float* __restrict__ ema_w,
                            float* __restrict__ out_ew,
                            float* __restrict__ out_cb,
                            float* __restrict__ out_loss)
{
    int i = blockIdx.x * blockDim.x + threadIdx.x;  // 65536
    float e = 0.99f * ema_w[i] + 0.01f * g_dw[i];
    out_ew[i] = e;
    int k = i >> 6;
    float n = g_n;
    float cs = (g_ncs[k] + 1e-5f) / (n + 1024.0f * 1e-5f) * n;
    out_cb[i] = e / cs;
    if (i == 0) out_loss[0] = g_loss * (1.0f / 8388608.0f);  // 2^-23 == 1/(N*D)
}

// ---------------- launch ----------------
extern "C" void kernel_launch(void* const* d_in, const int* in_sizes, int n_in,
                              void* d_out, int out_size)
{
    const float* z            = (const float*)d_in[0];
    const float* codebook     = (const float*)d_in[1];
    const float* cluster_size = (const float*)d_in[2];
    const float* ema_w        = (const float*)d_in[3];
    float* out = (float*)d_out;

    // output packing: quantized_st | indices | loss | new_codebook | new_cluster_size | new_ema_w
    const size_t OFF_Q    = 0;
    const size_t OFF_IDX  = (size_t)N_TOKENS * CODE_DIM;          // 8388608
    const size_t OFF_LOSS = OFF_IDX + N_TOKENS;                   // 8519680
    const size_t OFF_CB   = OFF_LOSS + 1;                         // 8519681
    const size_t OFF_CS   = OFF_CB + NUM_CODES * CODE_DIM;        // 8585217
    const size_t OFF_EW   = OFF_CS + NUM_CODES;                   // 8586241

    cudaFuncSetAttribute(vq_main, cudaFuncAttributeMaxDynamicSharedMemorySize, SMEM_TOTAL);

    vq_prep<<<256, 256>>>(codebook);
    vq_main<<<N_TOKENS / 128, 256, SMEM_TOTAL>>>(z, codebook, out + OFF_Q, out + OFF_IDX);
    vq_final_cs<<<1, NUM_CODES>>>(cluster_size, out + OFF_CS);
    vq_final_cb<<<(NUM_CODES * CODE_DIM) / 256, 256>>>(ema_w, out + OFF_EW,
                                                       out + OFF_CB, out + OFF_LOSS);
}

// round 15
// speedup vs baseline: 1.0597x; 1.0069x over previous
#include <cuda_runtime.h>
#include <cuda_fp16.h>
#include <cstdint>

#define N_TOKENS  131072
#define CODE_DIM  64
#define NUM_CODES 1024

// ---------------- device scratch (no allocations allowed) ----------------
__device__ float g_counts[NUM_CODES];
__device__ float g_dw[NUM_CODES * CODE_DIM];
__device__ float g_loss;
__device__ float g_ncs[NUM_CODES];
__device__ float g_n;
__device__ __align__(16) __half g_cb_h[NUM_CODES * CODE_DIM];
__device__ __align__(16) float g_cc[NUM_CODES];   // ||c||^2 + 256 (screen bias folded)

// ---------------- prep: zero scratch + fp16 codebook + cc ----------------
__global__ void vq_prep(const float* __restrict__ codebook) {
    int i = blockIdx.x * blockDim.x + threadIdx.x;   // 65536 threads
    g_dw[i] = 0.0f;
    if (i == 0) g_loss = 0.0f;
    if (i < NUM_CODES) {
        g_counts[i] = 0.0f;
        const float* c = codebook + (size_t)i * CODE_DIM;
        float s0 = 0.0f, s1 = 0.0f;
        #pragma unroll
        for (int k = 0; k < 32; k++) {
            float v = c[k];
            s0 += v * v;
            g_cb_h[i * CODE_DIM + k] = __float2half(v);
        }
        #pragma unroll
        for (int k = 32; k < 64; k++) {
            float v = c[k];
            s1 += v * v;
            g_cb_h[i * CODE_DIM + k] = __float2half(v);
        }
        g_cc[i] = (s0 + s1) + 256.0f;
    }
}

// ---------------- asm helpers ----------------
__device__ __forceinline__ void ldsm4(uint32_t (&r)[4], uint32_t addr) {
    asm volatile("ldmatrix.sync.aligned.m8n8.x4.shared.b16 {%0,%1,%2,%3}, [%4];"
                 : "=r"(r[0]), "=r"(r[1]), "=r"(r[2]), "=r"(r[3]) : "r"(addr));
}
__device__ __forceinline__ void mma16816(float (&d)[4], const uint32_t (&a)[4],
                                         const uint32_t* b) {
    asm volatile("mma.sync.aligned.m16n8k16.row.col.f32.f16.f16.f32 "
                 "{%0,%1,%2,%3}, {%4,%5,%6,%7}, {%8,%9}, {%0,%1,%2,%3};"
                 : "+f"(d[0]), "+f"(d[1]), "+f"(d[2]), "+f"(d[3])
                 : "r"(a[0]), "r"(a[1]), "r"(a[2]), "r"(a[3]),
                   "r"(b[0]), "r"(b[1]));
}
__device__ __forceinline__ void cp_async16(uint32_t dst, const void* src) {
    asm volatile("cp.async.cg.shared.global [%0], [%1], 16;" :: "r"(dst), "l"(src));
}
#define CP_COMMIT() asm volatile("cp.async.commit_group;")
#define CP_WAIT1()  asm volatile("cp.async.wait_group 1;" ::: "memory")
#define CP_WAIT0()  asm volatile("cp.async.wait_group 0;" ::: "memory")

// exact round-2-style d2 (sequential-FMA dot, half-split sumsq, (zz-2a)+cc)
__device__ __forceinline__ float exact_d2_g(const float* __restrict__ zrow,
                                            const float* __restrict__ c, float zz) {
    float a = 0.0f;
    for (int k = 0; k < CODE_DIM; k++) a = fmaf(zrow[k], c[k], a);
    float c0 = 0.0f, c1 = 0.0f;
    for (int k = 0; k < 32; k++)  { float v = c[k]; c0 += v * v; }
    for (int k = 32; k < 64; k++) { float v = c[k]; c1 += v * v; }
    return (zz - 2.0f * a) + (c0 + c1);
}

// merge two sorted triples -> sorted top-3 of the six
__device__ __forceinline__ void merge3(unsigned long long& a1, unsigned long long& a2,
                                       unsigned long long& a3,
                                       unsigned long long b1, unsigned long long b2,
                                       unsigned long long b3) {
    unsigned long long lo1 = min(a1, b1), hi1 = max(a1, b1);
    unsigned long long lo2 = min(a2, b2), hi2 = max(a2, b2);
    a1 = lo1;
    unsigned long long t = min(hi1, lo2), u = max(hi1, lo2);
    a2 = t;
    a3 = min(u, min(hi2, min(a3, b3)));
}

// smem byte offsets: 16 tiles of 64 codes, double-buffered
#define OFF_ZH   0               // 128 x 72 fp16 = 18432
#define OFF_CH   18432           // 2 bufs x 9216 (64 rows x 144B)
#define OFF_CC   36864           // 2 bufs x 256
#define OFF_RED  37376           // 128 x 4 x 32B = 16384
#define OFF_LP   53760           // 32 floats
#define SMEM_TOTAL 53888

// deferred epilogue of one 64-code tile: s = (cc+256) - 2*dot; 6-bit id keys, sorted top-3
__device__ __forceinline__ void epi_step(const float (&acc)[4][2][4], const float (&ccr)[4],
                                         int idb6, int (&k3)[8][3]) {
    #pragma unroll
    for (int mf = 0; mf < 4; mf++)
        #pragma unroll
        for (int rr = 0; rr < 2; rr++) {
            const int row = mf * 2 + rr;
            #pragma unroll
            for (int nf = 0; nf < 2; nf++)
                #pragma unroll
                for (int c = 0; c < 2; c++) {
                    float s = fmaf(acc[mf][nf][rr * 2 + c], -2.0f, ccr[nf * 2 + c]);
                    int key = (__float_as_int(s) & 0xFFFFFFC0) | (idb6 + nf * 2 + c);
                    int t1 = max(k3[row][0], key);
                    k3[row][0] = min(k3[row][0], key);
                    int t2 = max(k3[row][1], t1);
                    k3[row][1] = min(k3[row][1], t1);
                    k3[row][2] = min(k3[row][2], t2);
                }
        }
}

// ---------------- main: 1-pass fp16 mma + register-neutral deferred-epilogue pipeline ----
// 256 threads, 8 warps as 2(M) x 4(N); block = 128 tokens x 1024 codes,
// 16 tiles of 64 codes. Double 32-reg accumulator sets (total 64 = R9 budget):
// tile ct's HMMAs in flight while tile ct-1's top-3 epilogue runs.
__global__ __launch_bounds__(256, 1)
void vq_main(const float* __restrict__ z, const float* __restrict__ codebook,
             float* __restrict__ out_q, float* __restrict__ out_idx)
{
    extern __shared__ char smem_raw[];
    char* sm = smem_raw;
    const uint32_t sbase = (uint32_t)__cvta_generic_to_shared(sm);

    const int tid = threadIdx.x;
    const int token0 = blockIdx.x * 128;
    const int lane = tid & 31, wid = tid >> 5;
    const int wm = wid >> 2, wn = wid & 3;
    const int lrow = lane & 7, lmat = lane >> 3;
    const int g = lane >> 2, q4 = lane & 3;

    // ---- prefetch codebook tile 0 (buf 0) + cc via cp.async ----
    #pragma unroll
    for (int j = 0; j < 2; j++) {
        int c = tid + j * 256;                 // 0..511 16B chunks (8 per code row)
        int r = c >> 3, k16 = c & 7;
        const __half* src = g_cb_h + (size_t)r * 64 + k16 * 8;
        cp_async16(sbase + OFF_CH + r * 144 + k16 * 16, src);
    }
    if (tid < 16) cp_async16(sbase + OFF_CC + tid * 16, g_cc + tid * 4);
    CP_COMMIT();

    // ---- z tile: fp16 into smem (stride 72 halves) ----
    {
        int r = tid >> 1, h = tid & 1;
        const float4* zp = (const float4*)(z + (size_t)(token0 + r) * CODE_DIM) + h * 8;
        __half* zh = (__half*)(sm + OFF_ZH) + r * 72 + h * 32;
        #pragma unroll
        for (int v = 0; v < 8; v++) {
            float4 t4 = zp[v];
            zh[v * 4 + 0] = __float2half(t4.x);
            zh[v * 4 + 1] = __float2half(t4.y);
            zh[v * 4 + 2] = __float2half(t4.z);
            zh[v * 4 + 3] = __float2half(t4.w);
        }
    }

    // ldmatrix addressing (A mapping proven R5/R9; B is the 16-code variant of it)
    const int a_row = wm * 64 + (lmat & 1) * 8 + lrow;
    const int a_kof = (lmat >> 1) * 8;
    const int b_row = wn * 16 + (lmat >> 1) * 8 + lrow;
    const int b_kof = (lmat & 1) * 8;

    // sorted top-3 trackers per row: keys = (bits(s)&~63) | (tile*4 + nf*2 + c)
    int k3[8][3];
    #pragma unroll
    for (int r = 0; r < 8; r++) {
        k3[r][0] = 0x7FFFFFFF; k3[r][1] = 0x7FFFFFFF; k3[r][2] = 0x7FFFFFFF;
    }

    float acc[2][4][2][4];     // double accumulator sets, 32 regs each
    float ccr[2][4];           // cc values for each in-flight tile

    for (int ct = 0; ct < 16; ct++) {
        const int b = ct & 1;
        if (ct < 15) {       // prefetch tile ct+1 into buf b^1
            const int nb = b ^ 1;
            #pragma unroll
            for (int j = 0; j < 2; j++) {
                int c = tid + j * 256;
                int r = c >> 3, k16 = c & 7;
                const __half* src = g_cb_h + (size_t)((ct + 1) * 64 + r) * 64 + k16 * 8;
                cp_async16(sbase + OFF_CH + nb * 9216 + r * 144 + k16 * 16, src);
            }
            if (tid < 16) cp_async16(sbase + OFF_CC + nb * 256 + tid * 16,
                                     g_cc + (ct + 1) * 64 + tid * 4);
            CP_COMMIT();
            CP_WAIT1();
        } else {
            CP_WAIT0();
        }
        __syncthreads();     // tile ct staged & visible to all warps

        // cc for tile ct -> regs (consumed by the deferred epilogue next iteration)
        const float* ccs = (const float*)(sm + OFF_CC + b * 256);
        #pragma unroll
        for (int nf = 0; nf < 2; nf++)
            #pragma unroll
            for (int c = 0; c < 2; c++)
                ccr[b][nf * 2 + c] = ccs[wn * 16 + nf * 8 + q4 * 2 + c];

        // ldsm + issue HMMAs into acc[b]
        #pragma unroll
        for (int mf = 0; mf < 4; mf++)
            #pragma unroll
            for (int nf = 0; nf < 2; nf++)
                #pragma unroll
                for (int e = 0; e < 4; e++) acc[b][mf][nf][e] = 0.0f;

        const uint32_t s_ch = sbase + OFF_CH + b * 9216;
        #pragma unroll
        for (int kc = 0; kc < 4; kc++) {
            uint32_t ah[4][4], bh[4];
            #pragma unroll
            for (int mf = 0; mf < 4; mf++) {
                uint32_t off = (uint32_t)(((a_row + mf * 16) * 72 + kc * 16 + a_kof) * 2);
                ldsm4(ah[mf], sbase + OFF_ZH + off);
            }
            {
                uint32_t off = (uint32_t)((b_row * 72 + kc * 16 + b_kof) * 2);
                ldsm4(bh, s_ch + off);
            }
            #pragma unroll
            for (int mf = 0; mf < 4; mf++)
                #pragma unroll
                for (int nf = 0; nf < 2; nf++)
                    mma16816(acc[b][mf][nf], ah[mf], &bh[nf * 2]);
        }

        // deferred epilogue of tile ct-1 (independent regs -> overlaps in-flight HMMAs)
        if (ct > 0) epi_step(acc[b ^ 1], ccr[b ^ 1], (ct - 1) * 4, k3);
    }
    // tail epilogue: tile 15 (acc set 1)
    epi_step(acc[1], ccr[1], 60, k3);

    // ---- per-row: 64-bit keys (sorted already), quad shfl merge, stash per (token, wn) ----
    ulonglong4* red = (ulonglong4*)(sm + OFF_RED);
    const int base_nc = wn * 16 + q4 * 2;
    #pragma unroll
    for (int row = 0; row < 8; row++) {
        unsigned long long m1, m2, m3;
        {
            unsigned long long kk[3];
            #pragma unroll
            for (int j = 0; j < 3; j++) {
                int k = k3[row][j];
                int id6 = k & 63;
                unsigned long long code =
                    (unsigned)((id6 >> 2) * 64 + ((id6 >> 1) & 1) * 8 + base_nc + (id6 & 1));
                kk[j] = ((unsigned long long)(unsigned)(k & 0xFFFFFFC0) << 10) | code;
            }
            m1 = kk[0]; m2 = kk[1]; m3 = kk[2];
        }
        #pragma unroll
        for (int m = 1; m <= 2; m <<= 1) {
            unsigned long long M1 = __shfl_xor_sync(0xffffffffu, m1, m);
            unsigned long long M2 = __shfl_xor_sync(0xffffffffu, m2, m);
            unsigned long long M3 = __shfl_xor_sync(0xffffffffu, m3, m);
            merge3(m1, m2, m3, M1, M2, M3);
        }
        if (q4 == 0) {
            int tok = wm * 64 + (row >> 1) * 16 + (row & 1) * 8 + g;
            red[tok * 4 + wn] = make_ulonglong4(m1, m2, m3, 0ull);
        }
    }
    __syncthreads();

    // ---- writer: final merge, rescore near-ties, outputs + scatter stats ----
    float lsum = 0.0f;
    if (tid < 128) {
        const int t = tid;
        ulonglong4 p = red[t * 4];
        unsigned long long f1 = p.x, f2 = p.y, f3 = p.z;
        #pragma unroll
        for (int w = 1; w < 4; w++) {
            ulonglong4 q = red[t * 4 + w];
            merge3(f1, f2, f3, q.x, q.y, q.z);
        }
        int bi = (int)(f1 & 1023);
        const int token = token0 + t;
        const float* zrow = z + (size_t)token * CODE_DIM;

        float s1 = __int_as_float((int)(f1 >> 10));
        float s2 = __int_as_float((int)(f2 >> 10));
        if (s2 - s1 < 0.1f) {
            // near-tie: exact rescore of the screened top-3 (verified arithmetic)
            int c2 = (int)(f2 & 1023), c3 = (int)(f3 & 1023);
            float a0 = 0.0f, a1 = 0.0f;
            for (int k = 0; k < 32; k++)  { float v = zrow[k]; a0 += v * v; }
            for (int k = 32; k < 64; k++) { float v = zrow[k]; a1 += v * v; }
            float zz = a0 + a1;
            float d1 = exact_d2_g(zrow, codebook + (size_t)bi * CODE_DIM, zz);
            float d2 = exact_d2_g(zrow, codebook + (size_t)c2 * CODE_DIM, zz);
            float d3 = exact_d2_g(zrow, codebook + (size_t)c3 * CODE_DIM, zz);
            float bd = d1;
            if (d2 < bd || (d2 == bd && c2 < bi)) { bd = d2; bi = c2; }
            if (d3 < bd || (d3 == bd && c3 < bi)) { bd = d3; bi = c3; }
        }

        out_idx[token] = (float)bi;
        atomicAdd(&g_counts[bi], 1.0f);

        const float4* cb = (const float4*)(codebook + (size_t)bi * CODE_DIM);
        const float4* zp = (const float4*)zrow;
        float4* qo = (float4*)(out_q + (size_t)token * CODE_DIM);
        #pragma unroll
        for (int v = 0; v < 16; v++) {
            float4 q = cb[v];
            float4 zv = zp[v];
            int k = v * 4;
            float d0 = zv.x - q.x, d1 = zv.y - q.y, d2 = zv.z - q.z, d3 = zv.w - q.w;
            lsum += d0 * d0; lsum += d1 * d1; lsum += d2 * d2; lsum += d3 * d3;
            qo[v] = q;
            atomicAdd(&g_dw[bi * CODE_DIM + k + 0], zv.x);
            atomicAdd(&g_dw[bi * CODE_DIM + k + 1], zv.y);
            atomicAdd(&g_dw[bi * CODE_DIM + k + 2], zv.z);
            atomicAdd(&g_dw[bi * CODE_DIM + k + 3], zv.w);
        }
    }

    // ---- block reduction of commitment-loss partial ----
    #pragma unroll
    for (int o = 16; o > 0; o >>= 1) lsum += __shfl_down_sync(0xffffffffu, lsum, o);
    float* lpart = (float*)(sm + OFF_LP);
    if ((tid & 31) == 0) lpart[tid >> 5] = lsum;
    __syncthreads();
    if (tid == 0) {
        float s = 0.0f;
        #pragma unroll
        for (int w = 0; w < 8; w++) s += lpart[w];
        atomicAdd(&g_loss, s);
    }
}

// ---------------- finalize 1: new_cluster_size + its sum ----------------
__global__ void vq_final_cs(const float* __restrict__ cluster_size,
                            float* __restrict__ out_cs)
{
    int t = threadIdx.x;  // 1024 threads, 1 block
    float ncs = 0.99f * cluster_size[t] + 0.01f * g_counts[t];
    out_cs[t] = ncs;
    g_ncs[t] = ncs;

    float s = ncs;
    #pragma unroll
    for (int o = 16; o > 0; o >>= 1) s += __shfl_down_sync(0xffffffffu, s, o);
    __shared__ float p[32];
    if ((t & 31) == 0) p[t >> 5] = s;
    __syncthreads();
    if (t < 32) {
        float v = p[t];
        #pragma unroll
        for (int o = 16; o > 0; o >>= 1) v += __shfl_down_sync(0xffffffffu, v, o);
        if (t == 0) g_n = v;
    }
}

// ---------------- finalize 2: new_ema_w, new_codebook, loss ----------------
__global__ void vq_final_cb(const float* __restrict__ ema_w,
                            float* __restrict__ out_ew,
                            float* __restrict__ out_cb,
                            float* __restrict__ out_loss)
{
    int i = blockIdx.x * blockDim.x + threadIdx.x;  // 65536
    float e = 0.99f * ema_w[i] + 0.01f * g_dw[i];
    out_ew[i] = e;
    int k = i >> 6;
    float n = g_n;
    float cs = (g_ncs[k] + 1e-5f) / (n + 1024.0f * 1e-5f) * n;
    out_cb[i] = e / cs;
    if (i == 0) out_loss[0] = g_loss * (1.0f / 8388608.0f);  // 2^-23 == 1/(N*D)
}

// ---------------- launch ----------------
extern "C" void kernel_launch(void* const* d_in, const int* in_sizes, int n_in,
                              void* d_out, int out_size)
{
    const float* z            = (const float*)d_in[0];
    const float* codebook     = (const float*)d_in[1];
    const float* cluster_size = (const float*)d_in[2];
    const float* ema_w        = (const float*)d_in[3];
    float* out = (float*)d_out;

    // output packing: quantized_st | indices | loss | new_codebook | new_cluster_size | new_ema_w
    const size_t OFF_Q    = 0;
    const size_t OFF_IDX  = (size_t)N_TOKENS * CODE_DIM;          // 8388608
    const size_t OFF_LOSS = OFF_IDX + N_TOKENS;                   // 8519680
    const size_t OFF_CB   = OFF_LOSS + 1;                         // 8519681
    const size_t OFF_CS   = OFF_CB + NUM_CODES * CODE_DIM;        // 8585217
    const size_t OFF_EW   = OFF_CS + NUM_CODES;                   // 8586241

    cudaFuncSetAttribute(vq_main, cudaFuncAttributeMaxDynamicSharedMemorySize, SMEM_TOTAL);

    vq_prep<<<256, 256>>>(codebook);
    vq_main<<<N_TOKENS / 128, 256, SMEM_TOTAL>>>(z, codebook, out + OFF_Q, out + OFF_IDX);
    vq_final_cs<<<1, NUM_CODES>>>(cluster_size, out + OFF_CS);
    vq_final_cb<<<(NUM_CODES * CODE_DIM) / 256, 256>>>(ema_w, out + OFF_EW,
                                                       out + OFF_CB, out + OFF_LOSS);
}

// round 16
// speedup vs baseline: 1.3066x; 1.2330x over previous
#include <cuda_runtime.h>
#include <cuda_fp16.h>
#include <cstdint>

#define N_TOKENS  131072
#define CODE_DIM  64
#define NUM_CODES 1024
#define GRID_MAIN 148
#define N_TILES   (N_TOKENS / 128)   // 1024

// ---------------- device scratch (no allocations allowed) ----------------
__device__ float g_counts[NUM_CODES];
__device__ float g_dw[NUM_CODES * CODE_DIM];
__device__ float g_loss;
__device__ float g_ncs[NUM_CODES];
__device__ float g_n;
__device__ __align__(16) __half g_cb_h[NUM_CODES * CODE_DIM];
__device__ __align__(16) float g_cc[NUM_CODES];   // ||c||^2 + 256 (screen bias folded)

// ---------------- prep: zero scratch + fp16 codebook + cc ----------------
__global__ void vq_prep(const float* __restrict__ codebook) {
    int i = blockIdx.x * blockDim.x + threadIdx.x;   // 65536 threads
    g_dw[i] = 0.0f;
    if (i == 0) g_loss = 0.0f;
    if (i < NUM_CODES) {
        g_counts[i] = 0.0f;
        const float* c = codebook + (size_t)i * CODE_DIM;
        float s0 = 0.0f, s1 = 0.0f;
        #pragma unroll
        for (int k = 0; k < 32; k++) {
            float v = c[k];
            s0 += v * v;
            g_cb_h[i * CODE_DIM + k] = __float2half(v);
        }
        #pragma unroll
        for (int k = 32; k < 64; k++) {
            float v = c[k];
            s1 += v * v;
            g_cb_h[i * CODE_DIM + k] = __float2half(v);
        }
        g_cc[i] = (s0 + s1) + 256.0f;
    }
}

// ---------------- asm helpers ----------------
__device__ __forceinline__ void ldsm4(uint32_t (&r)[4], uint32_t addr) {
    asm volatile("ldmatrix.sync.aligned.m8n8.x4.shared.b16 {%0,%1,%2,%3}, [%4];"
                 : "=r"(r[0]), "=r"(r[1]), "=r"(r[2]), "=r"(r[3]) : "r"(addr));
}
__device__ __forceinline__ void mma16816(float (&d)[4], const uint32_t (&a)[4],
                                         const uint32_t* b) {
    asm volatile("mma.sync.aligned.m16n8k16.row.col.f32.f16.f16.f32 "
                 "{%0,%1,%2,%3}, {%4,%5,%6,%7}, {%8,%9}, {%0,%1,%2,%3};"
                 : "+f"(d[0]), "+f"(d[1]), "+f"(d[2]), "+f"(d[3])
                 : "r"(a[0]), "r"(a[1]), "r"(a[2]), "r"(a[3]),
                   "r"(b[0]), "r"(b[1]));
}
__device__ __forceinline__ void cp_async16(uint32_t dst, const void* src) {
    asm volatile("cp.async.cg.shared.global [%0], [%1], 16;" :: "r"(dst), "l"(src));
}
#define CP_COMMIT() asm volatile("cp.async.commit_group;")
#define CP_WAIT0()  asm volatile("cp.async.wait_group 0;" ::: "memory")

// exact round-2-style d2 (sequential-FMA dot, half-split sumsq, (zz-2a)+cc)
__device__ __forceinline__ float exact_d2_g(const float* __restrict__ zrow,
                                            const float* __restrict__ c, float zz) {
    float a = 0.0f;
    for (int k = 0; k < CODE_DIM; k++) a = fmaf(zrow[k], c[k], a);
    float c0 = 0.0f, c1 = 0.0f;
    for (int k = 0; k < 32; k++)  { float v = c[k]; c0 += v * v; }
    for (int k = 32; k < 64; k++) { float v = c[k]; c1 += v * v; }
    return (zz - 2.0f * a) + (c0 + c1);
}

// merge two sorted triples -> sorted top-3 of the six
__device__ __forceinline__ void merge3(unsigned long long& a1, unsigned long long& a2,
                                       unsigned long long& a3,
                                       unsigned long long b1, unsigned long long b2,
                                       unsigned long long b3) {
    unsigned long long lo1 = min(a1, b1), hi1 = max(a1, b1);
    unsigned long long lo2 = min(a2, b2), hi2 = max(a2, b2);
    a1 = lo1;
    unsigned long long t = min(hi1, lo2), u = max(hi1, lo2);
    a2 = t;
    a3 = min(u, min(hi2, min(a3, b3)));
}

// smem byte offsets: full fp16 codebook resident (persistent block amortizes staging)
#define OFF_ZH   0               // 128 x 72 fp16 = 18432
#define OFF_CH   18432           // 1024 x 144B (128B data + 16B pad) = 147456
#define OFF_CC   165888          // 1024 floats = 4096
#define OFF_RED  169984          // 128 x 4 x 32B = 16384
#define OFF_LP   186368          // 32 floats
#define SMEM_TOTAL 186496

// ---------------- main: persistent blocks, R9 loop body, staged-once codebook ----------
// 256 threads, 8 warps as 2(M) x 4(N). Grid = 148; each block owns ~7 token-tiles.
// Codebook (128 KB fp16) + cc staged ONCE per block; inner 8-code-tile loop has
// zero barriers and zero staging -- exactly R9's proven mma/epilogue body.
__global__ __launch_bounds__(256, 1)
void vq_main(const float* __restrict__ z, const float* __restrict__ codebook,
             float* __restrict__ out_q, float* __restrict__ out_idx)
{
    extern __shared__ char smem_raw[];
    char* sm = smem_raw;
    const uint32_t sbase = (uint32_t)__cvta_generic_to_shared(sm);

    const int tid = threadIdx.x;
    const int lane = tid & 31, wid = tid >> 5;
    const int wm = wid >> 2, wn = wid & 3;
    const int lrow = lane & 7, lmat = lane >> 3;
    const int g = lane >> 2, q4 = lane & 3;

    // ---- stage ENTIRE fp16 codebook + cc once (cp.async, overlapped with 1st z tile) ----
    #pragma unroll
    for (int j = 0; j < 32; j++) {
        int c = tid + j * 256;                 // 0..8191 16B chunks
        int r = c >> 3, k16 = c & 7;
        cp_async16(sbase + OFF_CH + r * 144 + k16 * 16, g_cb_h + (size_t)r * 64 + k16 * 8);
    }
    cp_async16(sbase + OFF_CC + tid * 16, g_cc + tid * 4);
    CP_COMMIT();

    // ldmatrix addressing (proven R5/R9 mapping)
    const int a_row = wm * 64 + (lmat & 1) * 8 + lrow;
    const int a_kof = (lmat >> 1) * 8;
    const int b_row = wn * 32 + (lmat >> 1) * 8 + lrow;
    const int b_kof = (lmat & 1) * 8;
    const float* ccs_all = (const float*)(sm + OFF_CC);
    ulonglong4* red = (ulonglong4*)(sm + OFF_RED);
    const int base_nc = wn * 32 + q4 * 2;

    float lsum = 0.0f;
    bool first = true;

    for (int tile = blockIdx.x; tile < N_TILES; tile += GRID_MAIN) {
        const int token0 = tile * 128;

        // ---- z tile: fp16 into smem (stride 72 halves) ----
        {
            int r = tid >> 1, h = tid & 1;
            const float4* zp = (const float4*)(z + (size_t)(token0 + r) * CODE_DIM) + h * 8;
            __half* zh = (__half*)(sm + OFF_ZH) + r * 72 + h * 32;
            #pragma unroll
            for (int v = 0; v < 8; v++) {
                float4 t4 = zp[v];
                zh[v * 4 + 0] = __float2half(t4.x);
                zh[v * 4 + 1] = __float2half(t4.y);
                zh[v * 4 + 2] = __float2half(t4.z);
                zh[v * 4 + 3] = __float2half(t4.w);
            }
        }
        if (first) { CP_WAIT0(); first = false; }
        __syncthreads();   // z (+ codebook on iter 0) resident

        // sorted top-3 trackers per (row, c): keys = (bits(s)&~31) | (ct*4+nf)  [R9 exact]
        int k3[8][2][3];
        #pragma unroll
        for (int r = 0; r < 8; r++)
            #pragma unroll
            for (int c = 0; c < 2; c++) {
                k3[r][c][0] = 0x7FFFFFFF; k3[r][c][1] = 0x7FFFFFFF; k3[r][c][2] = 0x7FFFFFFF;
            }

        for (int ct = 0; ct < 8; ct++) {
            float ccr[8];
            #pragma unroll
            for (int nf = 0; nf < 4; nf++)
                #pragma unroll
                for (int c = 0; c < 2; c++)
                    ccr[nf * 2 + c] = ccs_all[ct * 128 + wn * 32 + nf * 8 + q4 * 2 + c];

            float acc[4][4][4];
            #pragma unroll
            for (int mf = 0; mf < 4; mf++)
                #pragma unroll
                for (int nf = 0; nf < 4; nf++)
                    #pragma unroll
                    for (int e = 0; e < 4; e++) acc[mf][nf][e] = 0.0f;

            #pragma unroll
            for (int kc = 0; kc < 4; kc++) {
                uint32_t ah[4][4], bh[2][4];
                #pragma unroll
                for (int mf = 0; mf < 4; mf++) {
                    uint32_t off = (uint32_t)(((a_row + mf * 16) * 72 + kc * 16 + a_kof) * 2);
                    ldsm4(ah[mf], sbase + OFF_ZH + off);
                }
                #pragma unroll
                for (int np = 0; np < 2; np++) {
                    uint32_t off = (uint32_t)(((ct * 128 + b_row + np * 16) * 72
                                               + kc * 16 + b_kof) * 2);
                    ldsm4(bh[np], sbase + OFF_CH + off);
                }
                #pragma unroll
                for (int mf = 0; mf < 4; mf++)
                    #pragma unroll
                    for (int nf = 0; nf < 4; nf++)
                        mma16816(acc[mf][nf], ah[mf], &bh[nf >> 1][(nf & 1) * 2]);
            }

            // epilogue (R9 exact): s = (cc+256) - 2*dot, sorted top-3 insert
            const int idb = ct * 4;
            #pragma unroll
            for (int mf = 0; mf < 4; mf++)
                #pragma unroll
                for (int rr = 0; rr < 2; rr++) {
                    const int row = mf * 2 + rr;
                    #pragma unroll
                    for (int nf = 0; nf < 4; nf++)
                        #pragma unroll
                        for (int c = 0; c < 2; c++) {
                            float s = fmaf(acc[mf][nf][rr * 2 + c], -2.0f, ccr[nf * 2 + c]);
                            int key = (__float_as_int(s) & 0xFFFFFFE0) | (idb + nf);
                            int t1 = max(k3[row][c][0], key);
                            k3[row][c][0] = min(k3[row][c][0], key);
                            int t2 = max(k3[row][c][1], t1);
                            k3[row][c][1] = min(k3[row][c][1], t1);
                            k3[row][c][2] = min(k3[row][c][2], t2);
                        }
                }
        }

        // ---- per-row 64-bit keys, tracker + quad shfl merge, stash per (token, wn) ----
        #pragma unroll
        for (int row = 0; row < 8; row++) {
            unsigned long long m1, m2, m3;
            {
                unsigned long long kk[2][3];
                #pragma unroll
                for (int c = 0; c < 2; c++)
                    #pragma unroll
                    for (int j = 0; j < 3; j++) {
                        int k = k3[row][c][j];
                        int id = k & 31;
                        unsigned long long code =
                            (unsigned)((id >> 2) * 128 + (id & 3) * 8 + base_nc + c);
                        kk[c][j] = ((unsigned long long)(unsigned)(k & 0xFFFFFFE0) << 10) | code;
                    }
                m1 = kk[0][0]; m2 = kk[0][1]; m3 = kk[0][2];
                merge3(m1, m2, m3, kk[1][0], kk[1][1], kk[1][2]);
            }
            #pragma unroll
            for (int m = 1; m <= 2; m <<= 1) {
                unsigned long long M1 = __shfl_xor_sync(0xffffffffu, m1, m);
                unsigned long long M2 = __shfl_xor_sync(0xffffffffu, m2, m);
                unsigned long long M3 = __shfl_xor_sync(0xffffffffu, m3, m);
                merge3(m1, m2, m3, M1, M2, M3);
            }
            if (q4 == 0) {
                int tok = wm * 64 + (row >> 1) * 16 + (row & 1) * 8 + g;
                red[tok * 4 + wn] = make_ulonglong4(m1, m2, m3, 0ull);
            }
        }
        __syncthreads();   // red complete before writer reads

        // ---- writer: final merge, rescore near-ties, outputs + scatter stats ----
        if (tid < 128) {
            const int t = tid;
            ulonglong4 p = red[t * 4];
            unsigned long long f1 = p.x, f2 = p.y, f3 = p.z;
            #pragma unroll
            for (int w = 1; w < 4; w++) {
                ulonglong4 q = red[t * 4 + w];
                merge3(f1, f2, f3, q.x, q.y, q.z);
            }
            int bi = (int)(f1 & 1023);
            const int token = token0 + t;
            const float* zrow = z + (size_t)token * CODE_DIM;

            float s1 = __int_as_float((int)(f1 >> 10));
            float s2 = __int_as_float((int)(f2 >> 10));
            if (s2 - s1 < 0.1f) {
                int c2 = (int)(f2 & 1023), c3 = (int)(f3 & 1023);
                float a0 = 0.0f, a1 = 0.0f;
                for (int k = 0; k < 32; k++)  { float v = zrow[k]; a0 += v * v; }
                for (int k = 32; k < 64; k++) { float v = zrow[k]; a1 += v * v; }
                float zz = a0 + a1;
                float d1 = exact_d2_g(zrow, codebook + (size_t)bi * CODE_DIM, zz);
                float d2 = exact_d2_g(zrow, codebook + (size_t)c2 * CODE_DIM, zz);
                float d3 = exact_d2_g(zrow, codebook + (size_t)c3 * CODE_DIM, zz);
                float bd = d1;
                if (d2 < bd || (d2 == bd && c2 < bi)) { bd = d2; bi = c2; }
                if (d3 < bd || (d3 == bd && c3 < bi)) { bd = d3; bi = c3; }
            }

            out_idx[token] = (float)bi;
            atomicAdd(&g_counts[bi], 1.0f);

            const float4* cb = (const float4*)(codebook + (size_t)bi * CODE_DIM);
            const float4* zp = (const float4*)zrow;
            float4* qo = (float4*)(out_q + (size_t)token * CODE_DIM);
            #pragma unroll
            for (int v = 0; v < 16; v++) {
                float4 q = cb[v];
                float4 zv = zp[v];
                int k = v * 4;
                float d0 = zv.x - q.x, d1 = zv.y - q.y, d2 = zv.z - q.z, d3 = zv.w - q.w;
                lsum += d0 * d0; lsum += d1 * d1; lsum += d2 * d2; lsum += d3 * d3;
                qo[v] = q;
                atomicAdd(&g_dw[bi * CODE_DIM + k + 0], zv.x);
                atomicAdd(&g_dw[bi * CODE_DIM + k + 1], zv.y);
                atomicAdd(&g_dw[bi * CODE_DIM + k + 2], zv.z);
                atomicAdd(&g_dw[bi * CODE_DIM + k + 3], zv.w);
            }
        }
        __syncthreads();   // red consumed before next tile's reduction overwrites it
    }

    // ---- block reduction of commitment-loss partial (once, after all tiles) ----
    #pragma unroll
    for (int o = 16; o > 0; o >>= 1) lsum += __shfl_down_sync(0xffffffffu, lsum, o);
    float* lpart = (float*)(sm + OFF_LP);
    if ((tid & 31) == 0) lpart[tid >> 5] = lsum;
    __syncthreads();
    if (tid == 0) {
        float s = 0.0f;
        #pragma unroll
        for (int w = 0; w < 8; w++) s += lpart[w];
        atomicAdd(&g_loss, s);
    }
}

// ---------------- finalize 1: new_cluster_size + its sum ----------------
__global__ void vq_final_cs(const float* __restrict__ cluster_size,
                            float* __restrict__ out_cs)
{
    int t = threadIdx.x;  // 1024 threads, 1 block
    float ncs = 0.99f * cluster_size[t] + 0.01f * g_counts[t];
    out_cs[t] = ncs;
    g_ncs[t] = ncs;

    float s = ncs;
    #pragma unroll
    for (int o = 16; o > 0; o >>= 1) s += __shfl_down_sync(0xffffffffu, s, o);
    __shared__ float p[32];
    if ((t & 31) == 0) p[t >> 5] = s;
    __syncthreads();
    if (t < 32) {
        float v = p[t];
        #pragma unroll
        for (int o = 16; o > 0; o >>= 1) v += __shfl_down_sync(0xffffffffu, v, o);
        if (t == 0) g_n = v;
    }
}

// ---------------- finalize 2: new_ema_w, new_codebook, loss ----------------
__global__ void vq_final_cb(const float* __restrict__ ema_w,
                            float* __restrict__ out_ew,
                            float* __restrict__ out_cb,
                            float* __restrict__ out_loss)
{
    int i = blockIdx.x * blockDim.x + threadIdx.x;  // 65536
    float e = 0.99f * ema_w[i] + 0.01f * g_dw[i];
    out_ew[i] = e;
    int k = i >> 6;
    float n = g_n;
    float cs = (g_ncs[k] + 1e-5f) / (n + 1024.0f * 1e-5f) * n;
    out_cb[i] = e / cs;
    if (i == 0) out_loss[0] = g_loss * (1.0f / 8388608.0f);  // 2^-23 == 1/(N*D)
}

// ---------------- launch ----------------
extern "C" void kernel_launch(void* const* d_in, const int* in_sizes, int n_in,
                              void* d_out, int out_size)
{
    const float* z            = (const float*)d_in[0];
    const float* codebook     = (const float*)d_in[1];
    const float* cluster_size = (const float*)d_in[2];
    const float* ema_w        = (const float*)d_in[3];
    float* out = (float*)d_out;

    // output packing: quantized_st | indices | loss | new_codebook | new_cluster_size | new_ema_w
    const size_t OFF_Q    = 0;
    const size_t OFF_IDX  = (size_t)N_TOKENS * CODE_DIM;          // 8388608
    const size_t OFF_LOSS = OFF_IDX + N_TOKENS;                   // 8519680
    const size_t OFF_CB   = OFF_LOSS + 1;                         // 8519681
    const size_t OFF_CS   = OFF_CB + NUM_CODES * CODE_DIM;        // 8585217
    const size_t OFF_EW   = OFF_CS + NUM_CODES;                   // 8586241

    cudaFuncSetAttribute(vq_main, cudaFuncAttributeMaxDynamicSharedMemorySize, SMEM_TOTAL);

    vq_prep<<<256, 256>>>(codebook);
    vq_main<<<GRID_MAIN, 256, SMEM_TOTAL>>>(z, codebook, out + OFF_Q, out + OFF_IDX);
    vq_final_cs<<<1, NUM_CODES>>>(cluster_size, out + OFF_CS);
    vq_final_cb<<<(NUM_CODES * CODE_DIM) / 256, 256>>>(ema_w, out + OFF_EW,
                                                       out + OFF_CB, out + OFF_LOSS);
}